// round 15
// baseline (speedup 1.0000x reference)
#include <cuda_runtime.h>
#include <cuda_bf16.h>
#include <cstdint>

#define N_NODES 50000
#define N_EDGES 800000
#define HEADS 8
#define ADIM 8
#define HD 64            // HEADS*ADIM
#define CLAMP_V 5.0f
#define SCAN_BLK 196     // ceil(50000/256)

// ---------------- scratch (device globals: allocation-free rule) ----------------
__device__ __align__(16) float g_Q[N_NODES * HD];
__device__ __align__(16) float g_K[N_NODES * HD];
__device__ __align__(16) float g_V[N_NODES * HD];
__device__ __align__(16) float g_w[N_EDGES * HEADS];   // exp(clamped score)
__device__ int g_count[N_NODES];
__device__ int g_off[N_NODES + 1];
__device__ int g_cursor[N_NODES];
__device__ int g_order[N_EDGES];
__device__ int g_bsum[SCAN_BLK];
__device__ int g_boff[SCAN_BLK];
// precomputed EW hi/lo, PAIRED frag layout:
// g_Bhi2[col*16 + ks*4 + tig] = { word(k=ks*16+tig*2), word(k=ks*16+8+tig*2) }
__device__ __align__(16) uint2 g_Bhi2[128 * 16];
__device__ __align__(16) uint2 g_Blo2[128 * 16];

// ---------------- f32x2 packed FMA helpers (qkv kernel) ----------------
__device__ __forceinline__ unsigned long long pk2(float lo, float hi) {
    unsigned long long r;
    asm("mov.b64 %0, {%1, %2};" : "=l"(r) : "f"(lo), "f"(hi));
    return r;
}
__device__ __forceinline__ void fma2(unsigned long long& d, unsigned long long a, unsigned long long b) {
    asm("fma.rn.f32x2 %0, %1, %2, %0;" : "+l"(d) : "l"(a), "l"(b));
}
__device__ __forceinline__ float2 upk2(unsigned long long v) {
    float lo, hi;
    asm("mov.b64 {%0, %1}, %2;" : "=f"(lo), "=f"(hi) : "l"(v));
    return make_float2(lo, hi);
}

// bf16 split helpers
__device__ __forceinline__ uint32_t bfpack(float x, float y) {
    __nv_bfloat162 h = __floats2bfloat162_rn(x, y);
    return *reinterpret_cast<uint32_t*>(&h);
}

// mma.sync m16n8k16 bf16 (standard PTX)
__device__ __forceinline__ void mma16816(float* d,
    uint32_t a0, uint32_t a1, uint32_t a2, uint32_t a3, uint32_t b0, uint32_t b1) {
    asm volatile(
        "mma.sync.aligned.m16n8k16.row.col.f32.bf16.bf16.f32 "
        "{%0,%1,%2,%3}, {%4,%5,%6,%7}, {%8,%9}, {%0,%1,%2,%3};"
        : "+f"(d[0]), "+f"(d[1]), "+f"(d[2]), "+f"(d[3])
        : "r"(a0), "r"(a1), "r"(a2), "r"(a3), "r"(b0), "r"(b1));
}

// ---------------- kernel 1: QKV = x @ qkv_weight.T + bias ----------------
__global__ __launch_bounds__(256) void qkv_kernel(
    const float* __restrict__ x, const float* __restrict__ W, const float* __restrict__ bias)
{
    __shared__ float xS[64 * 68];
    __shared__ float wS[64 * 68];
    const int part = blockIdx.y;
    const int row0 = blockIdx.x * 64;
    const int tid = threadIdx.x;

    #pragma unroll
    for (int p = 0; p < 4; p++) {
        int idx = tid + p * 256;
        int r = idx >> 4, c4 = idx & 15;
        float4 v = make_float4(0.f, 0.f, 0.f, 0.f);
        int gr = row0 + r;
        if (gr < N_NODES) v = ((const float4*)x)[gr * 16 + c4];
        *(float4*)&xS[r * 68 + c4 * 4] = v;
    }
    #pragma unroll
    for (int p = 0; p < 4; p++) {
        int idx = tid + p * 256;
        int c = idx >> 4, f = idx & 15;
        float4 v = ((const float4*)W)[(part * 64 + c) * 16 + f];
        wS[(f * 4 + 0) * 68 + c] = v.x;
        wS[(f * 4 + 1) * 68 + c] = v.y;
        wS[(f * 4 + 2) * 68 + c] = v.z;
        wS[(f * 4 + 3) * 68 + c] = v.w;
    }
    __syncthreads();

    const int tx = tid & 15, ty = tid >> 4;
    unsigned long long acc[4][2];
    #pragma unroll
    for (int i = 0; i < 4; i++) { acc[i][0] = 0ull; acc[i][1] = 0ull; }

    #pragma unroll 4
    for (int k = 0; k < 64; k++) {
        float4 b = *(float4*)&wS[k * 68 + tx * 4];
        unsigned long long b0 = pk2(b.x, b.y), b1 = pk2(b.z, b.w);
        #pragma unroll
        for (int i = 0; i < 4; i++) {
            float a = xS[(ty * 4 + i) * 68 + k];
            unsigned long long a2 = pk2(a, a);
            fma2(acc[i][0], a2, b0);
            fma2(acc[i][1], a2, b1);
        }
    }

    float* outBase = (part == 0) ? g_Q : (part == 1 ? g_K : g_V);
    float4 bv = ((const float4*)bias)[part * 16 + tx];
    #pragma unroll
    for (int i = 0; i < 4; i++) {
        int gr = row0 + ty * 4 + i;
        if (gr < N_NODES) {
            float2 p0 = upk2(acc[i][0]), p1 = upk2(acc[i][1]);
            float4 o = make_float4(p0.x + bv.x, p0.y + bv.y, p1.x + bv.z, p1.y + bv.w);
            *(float4*)&outBase[gr * 64 + tx * 4] = o;
        }
    }
}

// ---------------- prep: EW -> hi/lo bf16, PAIRED frag layout (once) -----------
__global__ __launch_bounds__(128) void prep_kernel(const float* __restrict__ EW) {
    const int r = threadIdx.x;             // output col 0..127
    const float* row = EW + (size_t)r * 64;
    #pragma unroll
    for (int ks = 0; ks < 4; ks++) {
        #pragma unroll
        for (int tig = 0; tig < 4; tig++) {
            const int k0 = ks * 16 + tig * 2;
            uint32_t h[2], l[2];
            #pragma unroll
            for (int kp = 0; kp < 2; kp++) {
                float ax = row[k0 + kp * 8], ay = row[k0 + kp * 8 + 1];
                __nv_bfloat16 hx = __float2bfloat16(ax), hy = __float2bfloat16(ay);
                h[kp] = bfpack(__bfloat162float(hx), __bfloat162float(hy));
                l[kp] = bfpack(ax - __bfloat162float(hx), ay - __bfloat162float(hy));
            }
            const int p = r * 16 + ks * 4 + tig;
            g_Bhi2[p] = make_uint2(h[0], h[1]);
            g_Blo2[p] = make_uint2(l[0], l[1]);
        }
    }
}

// ---------------- CSR construction ----------------
__global__ void zero_kernel() {
    int i = blockIdx.x * blockDim.x + threadIdx.x;
    if (i < N_NODES) g_count[i] = 0;
}
__global__ __launch_bounds__(256) void scanA_kernel() {
    __shared__ int ws[8];
    int t = threadIdx.x, i = blockIdx.x * 256 + t;
    int v = (i < N_NODES) ? g_count[i] : 0;
    #pragma unroll
    for (int o = 16; o > 0; o >>= 1) v += __shfl_down_sync(0xffffffffu, v, o);
    if ((t & 31) == 0) ws[t >> 5] = v;
    __syncthreads();
    if (t == 0) {
        int s = 0;
        #pragma unroll
        for (int w = 0; w < 8; w++) s += ws[w];
        g_bsum[blockIdx.x] = s;
    }
}
__global__ __launch_bounds__(256) void scanB_kernel() {
    __shared__ int ws[8];
    int t = threadIdx.x, lane = t & 31, w = t >> 5;
    int v = (t < SCAN_BLK) ? g_bsum[t] : 0;
    int x = v;
    #pragma unroll
    for (int o = 1; o < 32; o <<= 1) {
        int y = __shfl_up_sync(0xffffffffu, x, o);
        if (lane >= o) x += y;
    }
    if (lane == 31) ws[w] = x;
    __syncthreads();
    if (t == 0) {
        int run = 0;
        #pragma unroll
        for (int k = 0; k < 8; k++) { int tmp = ws[k]; ws[k] = run; run += tmp; }
    }
    __syncthreads();
    if (t < SCAN_BLK) g_boff[t] = x - v + ws[w];
    if (t == 0) g_off[N_NODES] = N_EDGES;
}
__global__ __launch_bounds__(256) void scanC_kernel() {
    __shared__ int ws[8];
    int t = threadIdx.x, lane = t & 31, w = t >> 5;
    int i = blockIdx.x * 256 + t;
    int v = (i < N_NODES) ? g_count[i] : 0;
    int x = v;
    #pragma unroll
    for (int o = 1; o < 32; o <<= 1) {
        int y = __shfl_up_sync(0xffffffffu, x, o);
        if (lane >= o) x += y;
    }
    if (lane == 31) ws[w] = x;
    __syncthreads();
    if (t == 0) {
        int run = 0;
        #pragma unroll
        for (int k = 0; k < 8; k++) { int tmp = ws[k]; ws[k] = run; run += tmp; }
    }
    __syncthreads();
    if (i < N_NODES) {
        int excl = x - v + ws[w] + g_boff[blockIdx.x];
        g_off[i] = excl;
        g_cursor[i] = excl;
    }
}
__global__ void scatter_kernel(const int* __restrict__ eidx) {
    int e = blockIdx.x * blockDim.x + threadIdx.x;
    if (e < N_EDGES) {
        int dst = eidx[e];
        int pos = atomicAdd(&g_cursor[dst], 1);
        g_order[pos] = e;
    }
}

// ---------------- kernel 2: barrier-free split-bf16 HMMA edge GEMM ------------
// Same as R14 (best) except B frags now come from the PAIRED layout:
// one LDG.64 per frag instead of two LDG.32 -> mainloop LDG 160 -> 96/thread.
// Warp (wm, wn): edges wm*32..+31, cols {wn*32..+31} u {64+wn*32..+31}.
__global__ __launch_bounds__(256, 2) void edge_kernel(
    const float* __restrict__ cf,
    const float* __restrict__ Ebias, const int* __restrict__ eidx,
    const float* __restrict__ Aw, float* __restrict__ conn_out)
{
    const int tid = threadIdx.x;
    const int e0 = blockIdx.x * 128;
    const int wid = tid >> 5, lane = tid & 31;
    const int gid = lane >> 2, tig = lane & 3;
    const int wm = wid >> 1;               // m-group: edges wm*32..+31
    const int wn = wid & 1;                // n-half
    const int m0 = wm * 32;
    const int wn32 = wn * 32;

    // fused count_kernel: wn==0 warps cover their 32 edges
    if (wn == 0) {
        int dv = __ldg(&eidx[e0 + m0 + lane]);
        atomicAdd(&g_count[dv], 1);
    }

    float d[2][8][4];
    #pragma unroll
    for (int mt = 0; mt < 2; mt++)
        #pragma unroll
        for (int nt = 0; nt < 8; nt++)
            #pragma unroll
            for (int p = 0; p < 4; p++) d[mt][nt][p] = 0.f;

    #pragma unroll
    for (int ks = 0; ks < 4; ks++) {
        const int ke = ks * 16 + tig * 2;  // first k element of this thread's pair
        uint32_t ah[2][4], al[2][4];
        #pragma unroll
        for (int mt = 0; mt < 2; mt++) {
            #pragma unroll
            for (int rr = 0; rr < 2; rr++) {      // row +0 / +8
                const int row = e0 + m0 + mt * 16 + rr * 8 + gid;
                #pragma unroll
                for (int kp = 0; kp < 2; kp++) {  // k +0 / +8
                    float2 v = __ldg((const float2*)(cf + (size_t)row * 64 + ke + kp * 8));
                    uint32_t bx = __float_as_uint(v.x), by = __float_as_uint(v.y);
                    uint32_t h = __byte_perm(bx, by, 0x7632);
                    float hx = __uint_as_float(bx & 0xFFFF0000u);
                    float hy = __uint_as_float(by & 0xFFFF0000u);
                    uint32_t l = bfpack(v.x - hx, v.y - hy);
                    const int idx = rr + kp * 2;  // 0:(r0,k0) 1:(r8,k0) 2:(r0,k8) 3:(r8,k8)
                    ah[mt][idx] = h;
                    al[mt][idx] = l;
                }
            }
        }
        #pragma unroll
        for (int nt = 0; nt < 8; nt++) {
            const int cbase = wn32 + (nt & 3) * 8 + ((nt >> 2) * 64);
            const int w0 = (cbase + gid) * 16 + ks * 4 + tig;
            uint2 bh = __ldg(&g_Bhi2[w0]);
            uint2 bl = __ldg(&g_Blo2[w0]);
            #pragma unroll
            for (int mt = 0; mt < 2; mt++) {
                mma16816(d[mt][nt], ah[mt][0], ah[mt][1], ah[mt][2], ah[mt][3], bh.x, bh.y);
                mma16816(d[mt][nt], ah[mt][0], ah[mt][1], ah[mt][2], ah[mt][3], bl.x, bl.y);
                mma16816(d[mt][nt], al[mt][0], al[mt][1], al[mt][2], al[mt][3], bh.x, bh.y);
            }
        }
    }

    // ---- in-register epilogue: all constants via __ldg (L1-hot) ----
    const int c0 = tig * 2;
    #pragma unroll
    for (int er = 0; er < 4; er++) {
        const int mt = er >> 1, half = er & 1;
        const int el = m0 + mt * 16 + half * 8 + gid;
        const int e = e0 + el;
        const int dn = __ldg(&eidx[e]);
        const int sn = __ldg(&eidx[N_EDGES + e]);
        float wv[4];
        #pragma unroll
        for (int nt = 0; nt < 4; nt++) {
            const int cc = wn32 + nt * 8 + c0;
            const int h = wn * 4 + nt;
            float2 q2 = *(const float2*)&g_Q[(size_t)dn * 64 + cc];
            float2 k2 = *(const float2*)&g_K[(size_t)sn * 64 + cc];
            float qk0 = q2.x + k2.x, qk1 = q2.y + k2.y;
            float2 ebw = __ldg((const float2*)&Ebias[cc]);
            float2 ebb = __ldg((const float2*)&Ebias[64 + cc]);
            float ew0 = d[mt][nt][half * 2 + 0] + ebw.x;
            float ew1 = d[mt][nt][half * 2 + 1] + ebw.y;
            float eb0 = d[mt][nt + 4][half * 2 + 0] + ebb.x;
            float eb1 = d[mt][nt + 4][half * 2 + 1] + ebb.y;
            float c1a = qk0 * ew0;
            float c1b = qk1 * ew1;
            float conn0 = fmaxf(copysignf(sqrtf(fabsf(c1a)), c1a) + eb0, 0.f);
            float conn1 = fmaxf(copysignf(sqrtf(fabsf(c1b)), c1b) + eb1, 0.f);
            *(float2*)&conn_out[(long long)e * 64 + cc] = make_float2(conn0, conn1);
            float aw0 = __ldg(&Aw[c0 * 8 + h]);
            float aw1 = __ldg(&Aw[(c0 + 1) * 8 + h]);
            float sp = conn0 * aw0 + conn1 * aw1;
            sp += __shfl_xor_sync(0xffffffffu, sp, 1);
            sp += __shfl_xor_sync(0xffffffffu, sp, 2);
            wv[nt] = expf(fminf(fmaxf(sp, -CLAMP_V), CLAMP_V));
        }
        if (tig == 0)
            *(float4*)&g_w[(size_t)e * 8 + wn * 4] = make_float4(wv[0], wv[1], wv[2], wv[3]);
    }
}

// ---------------- kernel 3: per-node aggregation (warp per node, unroll 4) ----
__global__ __launch_bounds__(256) void node_kernel(
    const float* __restrict__ conn_out, const int* __restrict__ eidx,
    const float* __restrict__ Bw, float* __restrict__ No)
{
    __shared__ float bwS[512];
    int tid = threadIdx.x;
    bwS[tid] = Bw[tid];
    bwS[tid + 256] = Bw[tid + 256];
    __syncthreads();

    const int warp = tid >> 5, lane = tid & 31;
    const int n = blockIdx.x * 8 + warp;
    const int j0 = g_off[n], j1 = g_off[n + 1];
    const int h0 = lane >> 3, h1 = h0 + 4, c = lane & 7, base = lane & 24;
    const int* srcArr = eidx + N_EDGES;

    float s0 = 0.f, s1 = 0.f, agg0 = 0.f, agg1 = 0.f, rv0 = 0.f, rv1 = 0.f;
    int j = j0;
    for (; j + 3 < j1; j += 4) {
        int ee[4], ss[4];
        #pragma unroll
        for (int u = 0; u < 4; u++) ee[u] = g_order[j + u];
        #pragma unroll
        for (int u = 0; u < 4; u++) ss[u] = srcArr[ee[u]];
        #pragma unroll
        for (int u = 0; u < 4; u++) {
            int e1 = ee[u], sA = ss[u];
            float wA0 = g_w[e1 * 8 + h0], wA1 = g_w[e1 * 8 + h1];
            float cA0 = conn_out[(long long)e1 * 64 + lane];
            float cA1 = conn_out[(long long)e1 * 64 + 32 + lane];
            float vA0 = g_V[sA * 64 + lane], vA1 = g_V[sA * 64 + 32 + lane];
            s0 += wA0; s1 += wA1;
            agg0 = fmaf(wA0, vA0, agg0); rv0 = fmaf(wA0, cA0, rv0);
            agg1 = fmaf(wA1, vA1, agg1); rv1 = fmaf(wA1, cA1, rv1);
        }
    }
    for (; j < j1; j++) {
        int e1 = g_order[j];
        int sA = srcArr[e1];
        float wA0 = g_w[e1 * 8 + h0], wA1 = g_w[e1 * 8 + h1];
        float cA0 = conn_out[(long long)e1 * 64 + lane];
        float cA1 = conn_out[(long long)e1 * 64 + 32 + lane];
        float vA0 = g_V[sA * 64 + lane], vA1 = g_V[sA * 64 + 32 + lane];
        s0 += wA0; s1 += wA1;
        agg0 = fmaf(wA0, vA0, agg0); rv0 = fmaf(wA0, cA0, rv0);
        agg1 = fmaf(wA1, vA1, agg1); rv1 = fmaf(wA1, cA1, rv1);
    }
    float inv0 = (s0 > 0.f) ? 1.f / s0 : 0.f;
    float inv1 = (s1 > 0.f) ? 1.f / s1 : 0.f;
    float rn0 = rv0 * inv0, rn1 = rv1 * inv1;
    float o0 = 0.f, o1 = 0.f;
    #pragma unroll
    for (int dd = 0; dd < 8; dd++) {
        float r0 = __shfl_sync(0xffffffffu, rn0, base + dd);
        float r1 = __shfl_sync(0xffffffffu, rn1, base + dd);
        o0 = fmaf(r0, bwS[dd * 64 + h0 * 8 + c], o0);
        o1 = fmaf(r1, bwS[dd * 64 + h1 * 8 + c], o1);
    }
    No[n * 64 + lane] = fmaf(agg0, inv0, o0);
    No[n * 64 + 32 + lane] = fmaf(agg1, inv1, o1);
}

// ---------------- launch ----------------
extern "C" void kernel_launch(void* const* d_in, const int* in_sizes, int n_in,
                              void* d_out, int out_size)
{
    const float* x       = (const float*)d_in[0];
    const float* cf      = (const float*)d_in[1];
    const int*   eidx    = (const int*)d_in[2];
    const float* qkvW    = (const float*)d_in[3];
    const float* qkvB    = (const float*)d_in[4];
    const float* EW      = (const float*)d_in[5];
    const float* EB      = (const float*)d_in[6];
    const float* Aw      = (const float*)d_in[7];
    const float* Bw      = (const float*)d_in[8];

    float* No = (float*)d_out;
    float* conn_out = No + (size_t)N_NODES * 64;

    // ncu (-s 5 -c 1) profiles OUR 4th launch -> edge_kernel.
    zero_kernel<<<(N_NODES + 255) / 256, 256>>>();                         // 1
    qkv_kernel<<<dim3((N_NODES + 63) / 64, 3), 256>>>(x, qkvW, qkvB);      // 2
    prep_kernel<<<1, 128>>>(EW);                                           // 3
    edge_kernel<<<N_EDGES / 128, 256>>>(cf, EB, eidx, Aw, conn_out);       // 4 <- profiled
    scanA_kernel<<<SCAN_BLK, 256>>>();                                     // 5
    scanB_kernel<<<1, 256>>>();                                            // 6
    scanC_kernel<<<SCAN_BLK, 256>>>();                                     // 7
    scatter_kernel<<<(N_EDGES + 255) / 256, 256>>>(eidx);                  // 8
    node_kernel<<<N_NODES / 8, 256>>>(conn_out, eidx, Bw, No);             // 9
}

// round 16
// speedup vs baseline: 1.0633x; 1.0633x over previous
#include <cuda_runtime.h>
#include <cuda_bf16.h>
#include <cstdint>

#define N_NODES 50000
#define N_EDGES 800000
#define HEADS 8
#define ADIM 8
#define HD 64            // HEADS*ADIM
#define CLAMP_V 5.0f
#define SCAN_BLK 196     // ceil(50000/256)

// ---------------- scratch (device globals: allocation-free rule) ----------------
__device__ __align__(16) float g_Q[N_NODES * HD];
__device__ __align__(16) float g_K[N_NODES * HD];
__device__ __align__(16) float g_V[N_NODES * HD];
__device__ __align__(16) float g_w[N_EDGES * HEADS];   // exp(clamped score)
__device__ int g_count[N_NODES];
__device__ int g_off[N_NODES + 1];
__device__ int g_cursor[N_NODES];
__device__ int g_order[N_EDGES];
__device__ int g_bsum[SCAN_BLK];
__device__ int g_boff[SCAN_BLK];
// precomputed EW hi/lo in frag layout (row stride 36 words = 144B)
// R15 lesson: the "paired" uint2 layout REGRESSED (L1 wavefronts up);
// this stride-36 word layout is the measured-best B path.
__device__ __align__(16) unsigned g_Bhi[128 * 36];
__device__ __align__(16) unsigned g_Blo[128 * 36];

// ---------------- f32x2 packed FMA helpers (qkv kernel) ----------------
__device__ __forceinline__ unsigned long long pk2(float lo, float hi) {
    unsigned long long r;
    asm("mov.b64 %0, {%1, %2};" : "=l"(r) : "f"(lo), "f"(hi));
    return r;
}
__device__ __forceinline__ void fma2(unsigned long long& d, unsigned long long a, unsigned long long b) {
    asm("fma.rn.f32x2 %0, %1, %2, %0;" : "+l"(d) : "l"(a), "l"(b));
}
__device__ __forceinline__ float2 upk2(unsigned long long v) {
    float lo, hi;
    asm("mov.b64 {%0, %1}, %2;" : "=f"(lo), "=f"(hi) : "l"(v));
    return make_float2(lo, hi);
}

// bf16 split helpers
__device__ __forceinline__ uint32_t bfpack(float x, float y) {
    __nv_bfloat162 h = __floats2bfloat162_rn(x, y);
    return *reinterpret_cast<uint32_t*>(&h);
}

// mma.sync m16n8k16 bf16 (standard PTX)
__device__ __forceinline__ void mma16816(float* d,
    uint32_t a0, uint32_t a1, uint32_t a2, uint32_t a3, uint32_t b0, uint32_t b1) {
    asm volatile(
        "mma.sync.aligned.m16n8k16.row.col.f32.bf16.bf16.f32 "
        "{%0,%1,%2,%3}, {%4,%5,%6,%7}, {%8,%9}, {%0,%1,%2,%3};"
        : "+f"(d[0]), "+f"(d[1]), "+f"(d[2]), "+f"(d[3])
        : "r"(a0), "r"(a1), "r"(a2), "r"(a3), "r"(b0), "r"(b1));
}

// ---------------- kernel 1: QKV = x @ qkv_weight.T + bias ----------------
__global__ __launch_bounds__(256) void qkv_kernel(
    const float* __restrict__ x, const float* __restrict__ W, const float* __restrict__ bias)
{
    __shared__ float xS[64 * 68];
    __shared__ float wS[64 * 68];
    const int part = blockIdx.y;
    const int row0 = blockIdx.x * 64;
    const int tid = threadIdx.x;

    #pragma unroll
    for (int p = 0; p < 4; p++) {
        int idx = tid + p * 256;
        int r = idx >> 4, c4 = idx & 15;
        float4 v = make_float4(0.f, 0.f, 0.f, 0.f);
        int gr = row0 + r;
        if (gr < N_NODES) v = ((const float4*)x)[gr * 16 + c4];
        *(float4*)&xS[r * 68 + c4 * 4] = v;
    }
    #pragma unroll
    for (int p = 0; p < 4; p++) {
        int idx = tid + p * 256;
        int c = idx >> 4, f = idx & 15;
        float4 v = ((const float4*)W)[(part * 64 + c) * 16 + f];
        wS[(f * 4 + 0) * 68 + c] = v.x;
        wS[(f * 4 + 1) * 68 + c] = v.y;
        wS[(f * 4 + 2) * 68 + c] = v.z;
        wS[(f * 4 + 3) * 68 + c] = v.w;
    }
    __syncthreads();

    const int tx = tid & 15, ty = tid >> 4;
    unsigned long long acc[4][2];
    #pragma unroll
    for (int i = 0; i < 4; i++) { acc[i][0] = 0ull; acc[i][1] = 0ull; }

    #pragma unroll 4
    for (int k = 0; k < 64; k++) {
        float4 b = *(float4*)&wS[k * 68 + tx * 4];
        unsigned long long b0 = pk2(b.x, b.y), b1 = pk2(b.z, b.w);
        #pragma unroll
        for (int i = 0; i < 4; i++) {
            float a = xS[(ty * 4 + i) * 68 + k];
            unsigned long long a2 = pk2(a, a);
            fma2(acc[i][0], a2, b0);
            fma2(acc[i][1], a2, b1);
        }
    }

    float* outBase = (part == 0) ? g_Q : (part == 1 ? g_K : g_V);
    float4 bv = ((const float4*)bias)[part * 16 + tx];
    #pragma unroll
    for (int i = 0; i < 4; i++) {
        int gr = row0 + ty * 4 + i;
        if (gr < N_NODES) {
            float2 p0 = upk2(acc[i][0]), p1 = upk2(acc[i][1]);
            float4 o = make_float4(p0.x + bv.x, p0.y + bv.y, p1.x + bv.z, p1.y + bv.w);
            *(float4*)&outBase[gr * 64 + tx * 4] = o;
        }
    }
}

// ---------------- prep: convert EW -> hi/lo bf16 frag layout (once) ----------------
__global__ __launch_bounds__(256) void prep_kernel(const float* __restrict__ EW) {
    const int tid = threadIdx.x;
    const int r = tid >> 1;
    const int cb = (tid & 1) * 32;
    const float4* brow = (const float4*)(EW + (size_t)r * 64 + cb);
    uint2* bh = (uint2*)g_Bhi;
    uint2* bl = (uint2*)g_Blo;
    #pragma unroll
    for (int q = 0; q < 8; q++) {
        float4 u = brow[q];
        __nv_bfloat16 hx = __float2bfloat16(u.x), hy = __float2bfloat16(u.y);
        __nv_bfloat16 hz = __float2bfloat16(u.z), hw = __float2bfloat16(u.w);
        uint32_t h0 = bfpack(__bfloat162float(hx), __bfloat162float(hy));
        uint32_t h1 = bfpack(__bfloat162float(hz), __bfloat162float(hw));
        uint32_t l0 = bfpack(u.x - __bfloat162float(hx), u.y - __bfloat162float(hy));
        uint32_t l1 = bfpack(u.z - __bfloat162float(hz), u.w - __bfloat162float(hw));
        int p = r * 18 + cb / 4 + q;       // uint2 index
        bh[p] = make_uint2(h0, h1);
        bl[p] = make_uint2(l0, l1);
    }
}

// ---------------- CSR construction ----------------
__global__ void zero_kernel() {
    int i = blockIdx.x * blockDim.x + threadIdx.x;
    if (i < N_NODES) g_count[i] = 0;
}
__global__ __launch_bounds__(256) void scanA_kernel() {
    __shared__ int ws[8];
    int t = threadIdx.x, i = blockIdx.x * 256 + t;
    int v = (i < N_NODES) ? g_count[i] : 0;
    #pragma unroll
    for (int o = 16; o > 0; o >>= 1) v += __shfl_down_sync(0xffffffffu, v, o);
    if ((t & 31) == 0) ws[t >> 5] = v;
    __syncthreads();
    if (t == 0) {
        int s = 0;
        #pragma unroll
        for (int w = 0; w < 8; w++) s += ws[w];
        g_bsum[blockIdx.x] = s;
    }
}
__global__ __launch_bounds__(256) void scanB_kernel() {
    __shared__ int ws[8];
    int t = threadIdx.x, lane = t & 31, w = t >> 5;
    int v = (t < SCAN_BLK) ? g_bsum[t] : 0;
    int x = v;
    #pragma unroll
    for (int o = 1; o < 32; o <<= 1) {
        int y = __shfl_up_sync(0xffffffffu, x, o);
        if (lane >= o) x += y;
    }
    if (lane == 31) ws[w] = x;
    __syncthreads();
    if (t == 0) {
        int run = 0;
        #pragma unroll
        for (int k = 0; k < 8; k++) { int tmp = ws[k]; ws[k] = run; run += tmp; }
    }
    __syncthreads();
    if (t < SCAN_BLK) g_boff[t] = x - v + ws[w];
    if (t == 0) g_off[N_NODES] = N_EDGES;
}
__global__ __launch_bounds__(256) void scanC_kernel() {
    __shared__ int ws[8];
    int t = threadIdx.x, lane = t & 31, w = t >> 5;
    int i = blockIdx.x * 256 + t;
    int v = (i < N_NODES) ? g_count[i] : 0;
    int x = v;
    #pragma unroll
    for (int o = 1; o < 32; o <<= 1) {
        int y = __shfl_up_sync(0xffffffffu, x, o);
        if (lane >= o) x += y;
    }
    if (lane == 31) ws[w] = x;
    __syncthreads();
    if (t == 0) {
        int run = 0;
        #pragma unroll
        for (int k = 0; k < 8; k++) { int tmp = ws[k]; ws[k] = run; run += tmp; }
    }
    __syncthreads();
    if (i < N_NODES) {
        int excl = x - v + ws[w] + g_boff[blockIdx.x];
        g_off[i] = excl;
        g_cursor[i] = excl;
    }
}
__global__ void scatter_kernel(const int* __restrict__ eidx) {
    int e = blockIdx.x * blockDim.x + threadIdx.x;
    if (e < N_EDGES) {
        int dst = eidx[e];
        int pos = atomicAdd(&g_cursor[dst], 1);
        g_order[pos] = e;
    }
}

// ---------------- kernel 2: barrier-free split-bf16 HMMA edge GEMM (R14 best) --
// D[128 edges, 128 cols] = cf_tile @ EW^T via mma.sync m16n8k16 bf16, 3 passes.
// ZERO smem, ZERO __syncthreads: A fragments loaded straight from cf gmem
// and converted hi/lo in registers; B fragments __ldg'd from g_Bhi/g_Blo
// (stride-36 word layout, L1-hot). Warp (wm, wn): edges wm*32..+31,
// cols {wn*32..+31} u {64+wn*32..+31}.
__global__ __launch_bounds__(256, 2) void edge_kernel(
    const float* __restrict__ cf,
    const float* __restrict__ Ebias, const int* __restrict__ eidx,
    const float* __restrict__ Aw, float* __restrict__ conn_out)
{
    const int tid = threadIdx.x;
    const int e0 = blockIdx.x * 128;
    const int wid = tid >> 5, lane = tid & 31;
    const int gid = lane >> 2, tig = lane & 3;
    const int wm = wid >> 1;               // m-group: edges wm*32..+31
    const int wn = wid & 1;                // n-half
    const int m0 = wm * 32;
    const int wn32 = wn * 32;

    // fused count_kernel: wn==0 warps cover their 32 edges
    if (wn == 0) {
        int dv = __ldg(&eidx[e0 + m0 + lane]);
        atomicAdd(&g_count[dv], 1);
    }

    float d[2][8][4];
    #pragma unroll
    for (int mt = 0; mt < 2; mt++)
        #pragma unroll
        for (int nt = 0; nt < 8; nt++)
            #pragma unroll
            for (int p = 0; p < 4; p++) d[mt][nt][p] = 0.f;

    #pragma unroll
    for (int ks = 0; ks < 4; ks++) {
        const int ke = ks * 16 + tig * 2;  // first k element of this thread's pair
        uint32_t ah[2][4], al[2][4];
        #pragma unroll
        for (int mt = 0; mt < 2; mt++) {
            #pragma unroll
            for (int rr = 0; rr < 2; rr++) {      // row +0 / +8
                const int row = e0 + m0 + mt * 16 + rr * 8 + gid;
                #pragma unroll
                for (int kp = 0; kp < 2; kp++) {  // k +0 / +8
                    float2 v = __ldg((const float2*)(cf + (size_t)row * 64 + ke + kp * 8));
                    uint32_t bx = __float_as_uint(v.x), by = __float_as_uint(v.y);
                    uint32_t h = __byte_perm(bx, by, 0x7632);
                    float hx = __uint_as_float(bx & 0xFFFF0000u);
                    float hy = __uint_as_float(by & 0xFFFF0000u);
                    uint32_t l = bfpack(v.x - hx, v.y - hy);
                    const int idx = rr + kp * 2;  // 0:(r0,k0) 1:(r8,k0) 2:(r0,k8) 3:(r8,k8)
                    ah[mt][idx] = h;
                    al[mt][idx] = l;
                }
            }
        }
        #pragma unroll
        for (int nt = 0; nt < 8; nt++) {
            const int cbase = wn32 + (nt & 3) * 8 + ((nt >> 2) * 64);
            const int w0 = (cbase + gid) * 36 + ks * 8 + tig;
            uint32_t bh0 = __ldg(&g_Bhi[w0]);
            uint32_t bh1 = __ldg(&g_Bhi[w0 + 4]);
            uint32_t bl0 = __ldg(&g_Blo[w0]);
            uint32_t bl1 = __ldg(&g_Blo[w0 + 4]);
            #pragma unroll
            for (int mt = 0; mt < 2; mt++) {
                mma16816(d[mt][nt], ah[mt][0], ah[mt][1], ah[mt][2], ah[mt][3], bh0, bh1);
                mma16816(d[mt][nt], ah[mt][0], ah[mt][1], ah[mt][2], ah[mt][3], bl0, bl1);
                mma16816(d[mt][nt], al[mt][0], al[mt][1], al[mt][2], al[mt][3], bh0, bh1);
            }
        }
    }

    // ---- in-register epilogue: all constants via __ldg (L1-hot) ----
    const int c0 = tig * 2;
    #pragma unroll
    for (int er = 0; er < 4; er++) {
        const int mt = er >> 1, half = er & 1;
        const int el = m0 + mt * 16 + half * 8 + gid;
        const int e = e0 + el;
        const int dn = __ldg(&eidx[e]);
        const int sn = __ldg(&eidx[N_EDGES + e]);
        float wv[4];
        #pragma unroll
        for (int nt = 0; nt < 4; nt++) {
            const int cc = wn32 + nt * 8 + c0;
            const int h = wn * 4 + nt;
            float2 q2 = *(const float2*)&g_Q[(size_t)dn * 64 + cc];
            float2 k2 = *(const float2*)&g_K[(size_t)sn * 64 + cc];
            float qk0 = q2.x + k2.x, qk1 = q2.y + k2.y;
            float2 ebw = __ldg((const float2*)&Ebias[cc]);
            float2 ebb = __ldg((const float2*)&Ebias[64 + cc]);
            float ew0 = d[mt][nt][half * 2 + 0] + ebw.x;
            float ew1 = d[mt][nt][half * 2 + 1] + ebw.y;
            float eb0 = d[mt][nt + 4][half * 2 + 0] + ebb.x;
            float eb1 = d[mt][nt + 4][half * 2 + 1] + ebb.y;
            float c1a = qk0 * ew0;
            float c1b = qk1 * ew1;
            float conn0 = fmaxf(copysignf(sqrtf(fabsf(c1a)), c1a) + eb0, 0.f);
            float conn1 = fmaxf(copysignf(sqrtf(fabsf(c1b)), c1b) + eb1, 0.f);
            *(float2*)&conn_out[(long long)e * 64 + cc] = make_float2(conn0, conn1);
            float aw0 = __ldg(&Aw[c0 * 8 + h]);
            float aw1 = __ldg(&Aw[(c0 + 1) * 8 + h]);
            float sp = conn0 * aw0 + conn1 * aw1;
            sp += __shfl_xor_sync(0xffffffffu, sp, 1);
            sp += __shfl_xor_sync(0xffffffffu, sp, 2);
            wv[nt] = expf(fminf(fmaxf(sp, -CLAMP_V), CLAMP_V));
        }
        if (tig == 0)
            *(float4*)&g_w[(size_t)e * 8 + wn * 4] = make_float4(wv[0], wv[1], wv[2], wv[3]);
    }
}

// ---------------- kernel 3: per-node aggregation (warp per node, unroll 4) ----
__global__ __launch_bounds__(256) void node_kernel(
    const float* __restrict__ conn_out, const int* __restrict__ eidx,
    const float* __restrict__ Bw, float* __restrict__ No)
{
    __shared__ float bwS[512];
    int tid = threadIdx.x;
    bwS[tid] = Bw[tid];
    bwS[tid + 256] = Bw[tid + 256];
    __syncthreads();

    const int warp = tid >> 5, lane = tid & 31;
    const int n = blockIdx.x * 8 + warp;
    const int j0 = g_off[n], j1 = g_off[n + 1];
    const int h0 = lane >> 3, h1 = h0 + 4, c = lane & 7, base = lane & 24;
    const int* srcArr = eidx + N_EDGES;

    float s0 = 0.f, s1 = 0.f, agg0 = 0.f, agg1 = 0.f, rv0 = 0.f, rv1 = 0.f;
    int j = j0;
    for (; j + 3 < j1; j += 4) {
        int ee[4], ss[4];
        #pragma unroll
        for (int u = 0; u < 4; u++) ee[u] = g_order[j + u];
        #pragma unroll
        for (int u = 0; u < 4; u++) ss[u] = srcArr[ee[u]];
        #pragma unroll
        for (int u = 0; u < 4; u++) {
            int e1 = ee[u], sA = ss[u];
            float wA0 = g_w[e1 * 8 + h0], wA1 = g_w[e1 * 8 + h1];
            float cA0 = conn_out[(long long)e1 * 64 + lane];
            float cA1 = conn_out[(long long)e1 * 64 + 32 + lane];
            float vA0 = g_V[sA * 64 + lane], vA1 = g_V[sA * 64 + 32 + lane];
            s0 += wA0; s1 += wA1;
            agg0 = fmaf(wA0, vA0, agg0); rv0 = fmaf(wA0, cA0, rv0);
            agg1 = fmaf(wA1, vA1, agg1); rv1 = fmaf(wA1, cA1, rv1);
        }
    }
    for (; j < j1; j++) {
        int e1 = g_order[j];
        int sA = srcArr[e1];
        float wA0 = g_w[e1 * 8 + h0], wA1 = g_w[e1 * 8 + h1];
        float cA0 = conn_out[(long long)e1 * 64 + lane];
        float cA1 = conn_out[(long long)e1 * 64 + 32 + lane];
        float vA0 = g_V[sA * 64 + lane], vA1 = g_V[sA * 64 + 32 + lane];
        s0 += wA0; s1 += wA1;
        agg0 = fmaf(wA0, vA0, agg0); rv0 = fmaf(wA0, cA0, rv0);
        agg1 = fmaf(wA1, vA1, agg1); rv1 = fmaf(wA1, cA1, rv1);
    }
    float inv0 = (s0 > 0.f) ? 1.f / s0 : 0.f;
    float inv1 = (s1 > 0.f) ? 1.f / s1 : 0.f;
    float rn0 = rv0 * inv0, rn1 = rv1 * inv1;
    float o0 = 0.f, o1 = 0.f;
    #pragma unroll
    for (int dd = 0; dd < 8; dd++) {
        float r0 = __shfl_sync(0xffffffffu, rn0, base + dd);
        float r1 = __shfl_sync(0xffffffffu, rn1, base + dd);
        o0 = fmaf(r0, bwS[dd * 64 + h0 * 8 + c], o0);
        o1 = fmaf(r1, bwS[dd * 64 + h1 * 8 + c], o1);
    }
    No[n * 64 + lane] = fmaf(agg0, inv0, o0);
    No[n * 64 + 32 + lane] = fmaf(agg1, inv1, o1);
}

// ---------------- launch ----------------
extern "C" void kernel_launch(void* const* d_in, const int* in_sizes, int n_in,
                              void* d_out, int out_size)
{
    const float* x       = (const float*)d_in[0];
    const float* cf      = (const float*)d_in[1];
    const int*   eidx    = (const int*)d_in[2];
    const float* qkvW    = (const float*)d_in[3];
    const float* qkvB    = (const float*)d_in[4];
    const float* EW      = (const float*)d_in[5];
    const float* EB      = (const float*)d_in[6];
    const float* Aw      = (const float*)d_in[7];
    const float* Bw      = (const float*)d_in[8];

    float* No = (float*)d_out;
    float* conn_out = No + (size_t)N_NODES * 64;

    // ncu (-s 5 -c 1) profiles OUR 4th launch -> edge_kernel.
    zero_kernel<<<(N_NODES + 255) / 256, 256>>>();                         // 1
    qkv_kernel<<<dim3((N_NODES + 63) / 64, 3), 256>>>(x, qkvW, qkvB);      // 2
    prep_kernel<<<1, 256>>>(EW);                                           // 3
    edge_kernel<<<N_EDGES / 128, 256>>>(cf, EB, eidx, Aw, conn_out);       // 4 <- profiled
    scanA_kernel<<<SCAN_BLK, 256>>>();                                     // 5
    scanB_kernel<<<1, 256>>>();                                            // 6
    scanC_kernel<<<SCAN_BLK, 256>>>();                                     // 7
    scatter_kernel<<<(N_EDGES + 255) / 256, 256>>>(eidx);                  // 8
    node_kernel<<<N_NODES / 8, 256>>>(conn_out, eidx, Bw, No);             // 9
}

// round 17
// speedup vs baseline: 1.0928x; 1.0277x over previous
#include <cuda_runtime.h>
#include <cuda_bf16.h>
#include <cstdint>

#define N_NODES 50000
#define N_EDGES 800000
#define HEADS 8
#define ADIM 8
#define HD 64            // HEADS*ADIM
#define CLAMP_V 5.0f
#define SCAN_BLK 196     // ceil(50000/256)

// ---------------- scratch (device globals: allocation-free rule) ----------------
__device__ __align__(16) float g_Q[N_NODES * HD];
__device__ __align__(16) float g_K[N_NODES * HD];
__device__ __align__(16) float g_V[N_NODES * HD];
__device__ __align__(16) float g_w[N_EDGES * HEADS];   // exp(clamped score)
__device__ int g_count[N_NODES];
__device__ int g_off[N_NODES + 1];
__device__ int g_cursor[N_NODES];
__device__ int g_order[N_EDGES];
__device__ int g_bsum[SCAN_BLK];
__device__ int g_boff[SCAN_BLK];
// EW hi/lo, ks-major DENSE frag layout:
// g_Bhi2[ks*512 + col*4 + tig] = { word(k=ks*16+tig*2), word(k=ks*16+8+tig*2) }
// For a warp's (nt,ks) fetch: byte addr = ks*4096 + col*32 + tig*8 -> a dense
// 256B run per 8-col group (2 lines, 100% utilization). (R15's failed layout
// had col stride = 128B -> 8 lines at 25% utilization; this fixes that term.)
__device__ __align__(16) uint2 g_Bhi2[4 * 512];
__device__ __align__(16) uint2 g_Blo2[4 * 512];

// ---------------- f32x2 packed FMA helpers (qkv kernel) ----------------
__device__ __forceinline__ unsigned long long pk2(float lo, float hi) {
    unsigned long long r;
    asm("mov.b64 %0, {%1, %2};" : "=l"(r) : "f"(lo), "f"(hi));
    return r;
}
__device__ __forceinline__ void fma2(unsigned long long& d, unsigned long long a, unsigned long long b) {
    asm("fma.rn.f32x2 %0, %1, %2, %0;" : "+l"(d) : "l"(a), "l"(b));
}
__device__ __forceinline__ float2 upk2(unsigned long long v) {
    float lo, hi;
    asm("mov.b64 {%0, %1}, %2;" : "=f"(lo), "=f"(hi) : "l"(v));
    return make_float2(lo, hi);
}

// bf16 split helpers
__device__ __forceinline__ uint32_t bfpack(float x, float y) {
    __nv_bfloat162 h = __floats2bfloat162_rn(x, y);
    return *reinterpret_cast<uint32_t*>(&h);
}

// mma.sync m16n8k16 bf16 (standard PTX)
__device__ __forceinline__ void mma16816(float* d,
    uint32_t a0, uint32_t a1, uint32_t a2, uint32_t a3, uint32_t b0, uint32_t b1) {
    asm volatile(
        "mma.sync.aligned.m16n8k16.row.col.f32.bf16.bf16.f32 "
        "{%0,%1,%2,%3}, {%4,%5,%6,%7}, {%8,%9}, {%0,%1,%2,%3};"
        : "+f"(d[0]), "+f"(d[1]), "+f"(d[2]), "+f"(d[3])
        : "r"(a0), "r"(a1), "r"(a2), "r"(a3), "r"(b0), "r"(b1));
}

// ---------------- kernel 1: QKV = x @ qkv_weight.T + bias ----------------
__global__ __launch_bounds__(256) void qkv_kernel(
    const float* __restrict__ x, const float* __restrict__ W, const float* __restrict__ bias)
{
    __shared__ float xS[64 * 68];
    __shared__ float wS[64 * 68];
    const int part = blockIdx.y;
    const int row0 = blockIdx.x * 64;
    const int tid = threadIdx.x;

    #pragma unroll
    for (int p = 0; p < 4; p++) {
        int idx = tid + p * 256;
        int r = idx >> 4, c4 = idx & 15;
        float4 v = make_float4(0.f, 0.f, 0.f, 0.f);
        int gr = row0 + r;
        if (gr < N_NODES) v = ((const float4*)x)[gr * 16 + c4];
        *(float4*)&xS[r * 68 + c4 * 4] = v;
    }
    #pragma unroll
    for (int p = 0; p < 4; p++) {
        int idx = tid + p * 256;
        int c = idx >> 4, f = idx & 15;
        float4 v = ((const float4*)W)[(part * 64 + c) * 16 + f];
        wS[(f * 4 + 0) * 68 + c] = v.x;
        wS[(f * 4 + 1) * 68 + c] = v.y;
        wS[(f * 4 + 2) * 68 + c] = v.z;
        wS[(f * 4 + 3) * 68 + c] = v.w;
    }
    __syncthreads();

    const int tx = tid & 15, ty = tid >> 4;
    unsigned long long acc[4][2];
    #pragma unroll
    for (int i = 0; i < 4; i++) { acc[i][0] = 0ull; acc[i][1] = 0ull; }

    #pragma unroll 4
    for (int k = 0; k < 64; k++) {
        float4 b = *(float4*)&wS[k * 68 + tx * 4];
        unsigned long long b0 = pk2(b.x, b.y), b1 = pk2(b.z, b.w);
        #pragma unroll
        for (int i = 0; i < 4; i++) {
            float a = xS[(ty * 4 + i) * 68 + k];
            unsigned long long a2 = pk2(a, a);
            fma2(acc[i][0], a2, b0);
            fma2(acc[i][1], a2, b1);
        }
    }

    float* outBase = (part == 0) ? g_Q : (part == 1 ? g_K : g_V);
    float4 bv = ((const float4*)bias)[part * 16 + tx];
    #pragma unroll
    for (int i = 0; i < 4; i++) {
        int gr = row0 + ty * 4 + i;
        if (gr < N_NODES) {
            float2 p0 = upk2(acc[i][0]), p1 = upk2(acc[i][1]);
            float4 o = make_float4(p0.x + bv.x, p0.y + bv.y, p1.x + bv.z, p1.y + bv.w);
            *(float4*)&outBase[gr * 64 + tx * 4] = o;
        }
    }
}

// ---------------- prep: EW -> hi/lo bf16, ks-major dense frag layout ----------
__global__ __launch_bounds__(128) void prep_kernel(const float* __restrict__ EW) {
    const int col = threadIdx.x;           // output col 0..127
    const float* row = EW + (size_t)col * 64;
    #pragma unroll
    for (int ks = 0; ks < 4; ks++) {
        #pragma unroll
        for (int tig = 0; tig < 4; tig++) {
            const int k0 = ks * 16 + tig * 2;
            uint32_t h[2], l[2];
            #pragma unroll
            for (int kp = 0; kp < 2; kp++) {
                float ax = row[k0 + kp * 8], ay = row[k0 + kp * 8 + 1];
                __nv_bfloat16 hx = __float2bfloat16(ax), hy = __float2bfloat16(ay);
                h[kp] = bfpack(__bfloat162float(hx), __bfloat162float(hy));
                l[kp] = bfpack(ax - __bfloat162float(hx), ay - __bfloat162float(hy));
            }
            const int p = ks * 512 + col * 4 + tig;
            g_Bhi2[p] = make_uint2(h[0], h[1]);
            g_Blo2[p] = make_uint2(l[0], l[1]);
        }
    }
}

// ---------------- CSR construction ----------------
__global__ void zero_kernel() {
    int i = blockIdx.x * blockDim.x + threadIdx.x;
    if (i < N_NODES) g_count[i] = 0;
}
__global__ __launch_bounds__(256) void scanA_kernel() {
    __shared__ int ws[8];
    int t = threadIdx.x, i = blockIdx.x * 256 + t;
    int v = (i < N_NODES) ? g_count[i] : 0;
    #pragma unroll
    for (int o = 16; o > 0; o >>= 1) v += __shfl_down_sync(0xffffffffu, v, o);
    if ((t & 31) == 0) ws[t >> 5] = v;
    __syncthreads();
    if (t == 0) {
        int s = 0;
        #pragma unroll
        for (int w = 0; w < 8; w++) s += ws[w];
        g_bsum[blockIdx.x] = s;
    }
}
__global__ __launch_bounds__(256) void scanB_kernel() {
    __shared__ int ws[8];
    int t = threadIdx.x, lane = t & 31, w = t >> 5;
    int v = (t < SCAN_BLK) ? g_bsum[t] : 0;
    int x = v;
    #pragma unroll
    for (int o = 1; o < 32; o <<= 1) {
        int y = __shfl_up_sync(0xffffffffu, x, o);
        if (lane >= o) x += y;
    }
    if (lane == 31) ws[w] = x;
    __syncthreads();
    if (t == 0) {
        int run = 0;
        #pragma unroll
        for (int k = 0; k < 8; k++) { int tmp = ws[k]; ws[k] = run; run += tmp; }
    }
    __syncthreads();
    if (t < SCAN_BLK) g_boff[t] = x - v + ws[w];
    if (t == 0) g_off[N_NODES] = N_EDGES;
}
__global__ __launch_bounds__(256) void scanC_kernel() {
    __shared__ int ws[8];
    int t = threadIdx.x, lane = t & 31, w = t >> 5;
    int i = blockIdx.x * 256 + t;
    int v = (i < N_NODES) ? g_count[i] : 0;
    int x = v;
    #pragma unroll
    for (int o = 1; o < 32; o <<= 1) {
        int y = __shfl_up_sync(0xffffffffu, x, o);
        if (lane >= o) x += y;
    }
    if (lane == 31) ws[w] = x;
    __syncthreads();
    if (t == 0) {
        int run = 0;
        #pragma unroll
        for (int k = 0; k < 8; k++) { int tmp = ws[k]; ws[k] = run; run += tmp; }
    }
    __syncthreads();
    if (i < N_NODES) {
        int excl = x - v + ws[w] + g_boff[blockIdx.x];
        g_off[i] = excl;
        g_cursor[i] = excl;
    }
}
__global__ void scatter_kernel(const int* __restrict__ eidx) {
    int e = blockIdx.x * blockDim.x + threadIdx.x;
    if (e < N_EDGES) {
        int dst = eidx[e];
        int pos = atomicAdd(&g_cursor[dst], 1);
        g_order[pos] = e;
    }
}

// ---------------- kernel 2: barrier-free split-bf16 HMMA edge GEMM ------------
// R16 structure; B frags from the ks-major DENSE layout (one coalesced
// LDG.64 per frag, 2 lines/warp-fetch instead of 8).
// Warp (wm, wn): edges wm*32..+31, cols {wn*32..+31} u {64+wn*32..+31}.
__global__ __launch_bounds__(256, 2) void edge_kernel(
    const float* __restrict__ cf,
    const float* __restrict__ Ebias, const int* __restrict__ eidx,
    const float* __restrict__ Aw, float* __restrict__ conn_out)
{
    const int tid = threadIdx.x;
    const int e0 = blockIdx.x * 128;
    const int wid = tid >> 5, lane = tid & 31;
    const int gid = lane >> 2, tig = lane & 3;
    const int wm = wid >> 1;               // m-group: edges wm*32..+31
    const int wn = wid & 1;                // n-half
    const int m0 = wm * 32;
    const int wn32 = wn * 32;

    // fused count_kernel: wn==0 warps cover their 32 edges
    if (wn == 0) {
        int dv = __ldg(&eidx[e0 + m0 + lane]);
        atomicAdd(&g_count[dv], 1);
    }

    float d[2][8][4];
    #pragma unroll
    for (int mt = 0; mt < 2; mt++)
        #pragma unroll
        for (int nt = 0; nt < 8; nt++)
            #pragma unroll
            for (int p = 0; p < 4; p++) d[mt][nt][p] = 0.f;

    #pragma unroll
    for (int ks = 0; ks < 4; ks++) {
        const int ke = ks * 16 + tig * 2;  // first k element of this thread's pair
        uint32_t ah[2][4], al[2][4];
        #pragma unroll
        for (int mt = 0; mt < 2; mt++) {
            #pragma unroll
            for (int rr = 0; rr < 2; rr++) {      // row +0 / +8
                const int row = e0 + m0 + mt * 16 + rr * 8 + gid;
                #pragma unroll
                for (int kp = 0; kp < 2; kp++) {  // k +0 / +8
                    float2 v = __ldg((const float2*)(cf + (size_t)row * 64 + ke + kp * 8));
                    uint32_t bx = __float_as_uint(v.x), by = __float_as_uint(v.y);
                    uint32_t h = __byte_perm(bx, by, 0x7632);
                    float hx = __uint_as_float(bx & 0xFFFF0000u);
                    float hy = __uint_as_float(by & 0xFFFF0000u);
                    uint32_t l = bfpack(v.x - hx, v.y - hy);
                    const int idx = rr + kp * 2;  // 0:(r0,k0) 1:(r8,k0) 2:(r0,k8) 3:(r8,k8)
                    ah[mt][idx] = h;
                    al[mt][idx] = l;
                }
            }
        }
        #pragma unroll
        for (int nt = 0; nt < 8; nt++) {
            const int cbase = wn32 + (nt & 3) * 8 + ((nt >> 2) * 64);
            const int w0 = ks * 512 + (cbase + gid) * 4 + tig;
            uint2 bh = __ldg(&g_Bhi2[w0]);
            uint2 bl = __ldg(&g_Blo2[w0]);
            #pragma unroll
            for (int mt = 0; mt < 2; mt++) {
                mma16816(d[mt][nt], ah[mt][0], ah[mt][1], ah[mt][2], ah[mt][3], bh.x, bh.y);
                mma16816(d[mt][nt], ah[mt][0], ah[mt][1], ah[mt][2], ah[mt][3], bl.x, bl.y);
                mma16816(d[mt][nt], al[mt][0], al[mt][1], al[mt][2], al[mt][3], bh.x, bh.y);
            }
        }
    }

    // ---- in-register epilogue: all constants via __ldg (L1-hot) ----
    const int c0 = tig * 2;
    #pragma unroll
    for (int er = 0; er < 4; er++) {
        const int mt = er >> 1, half = er & 1;
        const int el = m0 + mt * 16 + half * 8 + gid;
        const int e = e0 + el;
        const int dn = __ldg(&eidx[e]);
        const int sn = __ldg(&eidx[N_EDGES + e]);
        float wv[4];
        #pragma unroll
        for (int nt = 0; nt < 4; nt++) {
            const int cc = wn32 + nt * 8 + c0;
            const int h = wn * 4 + nt;
            float2 q2 = *(const float2*)&g_Q[(size_t)dn * 64 + cc];
            float2 k2 = *(const float2*)&g_K[(size_t)sn * 64 + cc];
            float qk0 = q2.x + k2.x, qk1 = q2.y + k2.y;
            float2 ebw = __ldg((const float2*)&Ebias[cc]);
            float2 ebb = __ldg((const float2*)&Ebias[64 + cc]);
            float ew0 = d[mt][nt][half * 2 + 0] + ebw.x;
            float ew1 = d[mt][nt][half * 2 + 1] + ebw.y;
            float eb0 = d[mt][nt + 4][half * 2 + 0] + ebb.x;
            float eb1 = d[mt][nt + 4][half * 2 + 1] + ebb.y;
            float c1a = qk0 * ew0;
            float c1b = qk1 * ew1;
            float conn0 = fmaxf(copysignf(sqrtf(fabsf(c1a)), c1a) + eb0, 0.f);
            float conn1 = fmaxf(copysignf(sqrtf(fabsf(c1b)), c1b) + eb1, 0.f);
            *(float2*)&conn_out[(long long)e * 64 + cc] = make_float2(conn0, conn1);
            float aw0 = __ldg(&Aw[c0 * 8 + h]);
            float aw1 = __ldg(&Aw[(c0 + 1) * 8 + h]);
            float sp = conn0 * aw0 + conn1 * aw1;
            sp += __shfl_xor_sync(0xffffffffu, sp, 1);
            sp += __shfl_xor_sync(0xffffffffu, sp, 2);
            wv[nt] = expf(fminf(fmaxf(sp, -CLAMP_V), CLAMP_V));
        }
        if (tig == 0)
            *(float4*)&g_w[(size_t)e * 8 + wn * 4] = make_float4(wv[0], wv[1], wv[2], wv[3]);
    }
}

// ---------------- kernel 3: per-node aggregation (warp per node, unroll 4) ----
__global__ __launch_bounds__(256) void node_kernel(
    const float* __restrict__ conn_out, const int* __restrict__ eidx,
    const float* __restrict__ Bw, float* __restrict__ No)
{
    __shared__ float bwS[512];
    int tid = threadIdx.x;
    bwS[tid] = Bw[tid];
    bwS[tid + 256] = Bw[tid + 256];
    __syncthreads();

    const int warp = tid >> 5, lane = tid & 31;
    const int n = blockIdx.x * 8 + warp;
    const int j0 = g_off[n], j1 = g_off[n + 1];
    const int h0 = lane >> 3, h1 = h0 + 4, c = lane & 7, base = lane & 24;
    const int* srcArr = eidx + N_EDGES;

    float s0 = 0.f, s1 = 0.f, agg0 = 0.f, agg1 = 0.f, rv0 = 0.f, rv1 = 0.f;
    int j = j0;
    for (; j + 3 < j1; j += 4) {
        int ee[4], ss[4];
        #pragma unroll
        for (int u = 0; u < 4; u++) ee[u] = g_order[j + u];
        #pragma unroll
        for (int u = 0; u < 4; u++) ss[u] = srcArr[ee[u]];
        #pragma unroll
        for (int u = 0; u < 4; u++) {
            int e1 = ee[u], sA = ss[u];
            float wA0 = g_w[e1 * 8 + h0], wA1 = g_w[e1 * 8 + h1];
            float cA0 = conn_out[(long long)e1 * 64 + lane];
            float cA1 = conn_out[(long long)e1 * 64 + 32 + lane];
            float vA0 = g_V[sA * 64 + lane], vA1 = g_V[sA * 64 + 32 + lane];
            s0 += wA0; s1 += wA1;
            agg0 = fmaf(wA0, vA0, agg0); rv0 = fmaf(wA0, cA0, rv0);
            agg1 = fmaf(wA1, vA1, agg1); rv1 = fmaf(wA1, cA1, rv1);
        }
    }
    for (; j < j1; j++) {
        int e1 = g_order[j];
        int sA = srcArr[e1];
        float wA0 = g_w[e1 * 8 + h0], wA1 = g_w[e1 * 8 + h1];
        float cA0 = conn_out[(long long)e1 * 64 + lane];
        float cA1 = conn_out[(long long)e1 * 64 + 32 + lane];
        float vA0 = g_V[sA * 64 + lane], vA1 = g_V[sA * 64 + 32 + lane];
        s0 += wA0; s1 += wA1;
        agg0 = fmaf(wA0, vA0, agg0); rv0 = fmaf(wA0, cA0, rv0);
        agg1 = fmaf(wA1, vA1, agg1); rv1 = fmaf(wA1, cA1, rv1);
    }
    float inv0 = (s0 > 0.f) ? 1.f / s0 : 0.f;
    float inv1 = (s1 > 0.f) ? 1.f / s1 : 0.f;
    float rn0 = rv0 * inv0, rn1 = rv1 * inv1;
    float o0 = 0.f, o1 = 0.f;
    #pragma unroll
    for (int dd = 0; dd < 8; dd++) {
        float r0 = __shfl_sync(0xffffffffu, rn0, base + dd);
        float r1 = __shfl_sync(0xffffffffu, rn1, base + dd);
        o0 = fmaf(r0, bwS[dd * 64 + h0 * 8 + c], o0);
        o1 = fmaf(r1, bwS[dd * 64 + h1 * 8 + c], o1);
    }
    No[n * 64 + lane] = fmaf(agg0, inv0, o0);
    No[n * 64 + 32 + lane] = fmaf(agg1, inv1, o1);
}

// ---------------- launch ----------------
extern "C" void kernel_launch(void* const* d_in, const int* in_sizes, int n_in,
                              void* d_out, int out_size)
{
    const float* x       = (const float*)d_in[0];
    const float* cf      = (const float*)d_in[1];
    const int*   eidx    = (const int*)d_in[2];
    const float* qkvW    = (const float*)d_in[3];
    const float* qkvB    = (const float*)d_in[4];
    const float* EW      = (const float*)d_in[5];
    const float* EB      = (const float*)d_in[6];
    const float* Aw      = (const float*)d_in[7];
    const float* Bw      = (const float*)d_in[8];

    float* No = (float*)d_out;
    float* conn_out = No + (size_t)N_NODES * 64;

    // ncu (-s 5 -c 1) profiles OUR 4th launch -> edge_kernel.
    zero_kernel<<<(N_NODES + 255) / 256, 256>>>();                         // 1
    qkv_kernel<<<dim3((N_NODES + 63) / 64, 3), 256>>>(x, qkvW, qkvB);      // 2
    prep_kernel<<<1, 128>>>(EW);                                           // 3
    edge_kernel<<<N_EDGES / 128, 256>>>(cf, EB, eidx, Aw, conn_out);       // 4 <- profiled
    scanA_kernel<<<SCAN_BLK, 256>>>();                                     // 5
    scanB_kernel<<<1, 256>>>();                                            // 6
    scanC_kernel<<<SCAN_BLK, 256>>>();                                     // 7
    scatter_kernel<<<(N_EDGES + 255) / 256, 256>>>(eidx);                  // 8
    node_kernel<<<N_NODES / 8, 256>>>(conn_out, eidx, Bw, No);             // 9
}